// round 3
// baseline (speedup 1.0000x reference)
#include <cuda_runtime.h>
#include <cuda_bf16.h>

// out[b,d,n] = w[d] * in[b,d,n];  B=8, D=2048, N=2048, fp32.
// HBM-bound stream. R3: streaming cache hints (.cs evict-first) on the
// zero-reuse bulk data + unroll 8 front-batched LDG.128.

static constexpr int B = 8;
static constexpr int D = 2048;
static constexpr int N = 2048;
static constexpr long long TOTAL4 = (long long)B * D * N / 4;  // 8,388,608 float4
static constexpr int THREADS = 256;
static constexpr int UNROLL  = 8;
static constexpr int BLOCK_ELEMS = THREADS * UNROLL;           // 2048 float4 / block

__device__ __forceinline__ float4 ldg_cs_v4(const float4* p) {
    float4 v;
    asm volatile("ld.global.cs.v4.f32 {%0,%1,%2,%3}, [%4];"
                 : "=f"(v.x), "=f"(v.y), "=f"(v.z), "=f"(v.w)
                 : "l"(p));
    return v;
}

__device__ __forceinline__ void stg_cs_v4(float4* p, float4 v) {
    asm volatile("st.global.cs.v4.f32 [%0], {%1,%2,%3,%4};"
                 :: "l"(p), "f"(v.x), "f"(v.y), "f"(v.z), "f"(v.w)
                 : "memory");
}

__global__ void __launch_bounds__(THREADS)
channel_scale_kernel(const float4* __restrict__ in,
                     const float*  __restrict__ w,
                     float4*       __restrict__ out)
{
    long long base = (long long)blockIdx.x * BLOCK_ELEMS + threadIdx.x;

    // Front-batch 8 independent LDG.128 per thread.
    float4 v[UNROLL];
#pragma unroll
    for (int k = 0; k < UNROLL; k++) {
        v[k] = ldg_cs_v4(in + base + (long long)k * THREADS);
    }

#pragma unroll
    for (int k = 0; k < UNROLL; k++) {
        long long i = base + (long long)k * THREADS;
        // channel index: i4 / (N/4) % D ; N/4 = 512, D = 2048
        int d = (int)((i >> 9) & (D - 1));
        float s = __ldg(w + d);          // weights stay L2-cached (8 KB)
        v[k].x *= s; v[k].y *= s; v[k].z *= s; v[k].w *= s;
        stg_cs_v4(out + i, v[k]);
    }
}

extern "C" void kernel_launch(void* const* d_in, const int* in_sizes, int n_in,
                              void* d_out, int out_size)
{
    const float4* in = (const float4*)d_in[0];   // inputs [B, D, N] fp32
    const float*  w  = (const float*)d_in[1];    // attention_weights [D] fp32
    float4* out = (float4*)d_out;

    long long blocks = TOTAL4 / BLOCK_ELEMS;     // 4096, exact cover
    channel_scale_kernel<<<(unsigned)blocks, THREADS>>>(in, w, out);
}